// round 7
// baseline (speedup 1.0000x reference)
#include <cuda_runtime.h>
#include <cuda_bf16.h>
#include <cstdint>

#define PBY 80      // staged row pitch in bytes (40 bf16)
#define SEP 132     // sE pitch in f32

// smem offsets (bytes)
#define O_WQ 0
#define O_WK 512
#define O_AL 1024
#define O_M 1536
#define O_INV 2048
#define O_RED 2560        // 2048 f32 = 8192 B
#define O_AH 10752        // A hi  (128 x 40 bf16)
#define O_ALO 20992       // A lo
#define O_BH 31232        // B hi  (128 n-rows x 40 bf16)
#define O_BL 41472        // B lo
#define O_SE 51712        // 128 x 132 f32
#define SMEM_BYTES 119296

__device__ __forceinline__ uint32_t smem_u32(const void* p) {
    uint32_t a;
    asm("{ .reg .u64 t; cvta.to.shared.u64 t, %1; cvt.u32.u64 %0, t; }"
        : "=r"(a) : "l"(p));
    return a;
}
__device__ __forceinline__ float bf16rt(float x) {
    return __bfloat162float(__float2bfloat16(x));
}
__device__ __forceinline__ uint32_t bf16pair(float lo, float hi) {
    __nv_bfloat162 t = __floats2bfloat162_rn(lo, hi);  // lo -> low half
    return *(uint32_t*)&t;
}
__device__ __forceinline__ void ldsm4(uint32_t* r, uint32_t addr) {
    asm volatile("ldmatrix.sync.aligned.m8n8.x4.shared.b16 {%0,%1,%2,%3}, [%4];"
                 : "=r"(r[0]), "=r"(r[1]), "=r"(r[2]), "=r"(r[3]) : "r"(addr));
}
__device__ __forceinline__ void mma16(float* d, const uint32_t* a, const uint32_t* b) {
    asm volatile(
        "mma.sync.aligned.m16n8k16.row.col.f32.bf16.bf16.f32 "
        "{%0,%1,%2,%3}, {%4,%5,%6,%7}, {%8,%9}, {%0,%1,%2,%3};"
        : "+f"(d[0]), "+f"(d[1]), "+f"(d[2]), "+f"(d[3])
        : "r"(a[0]), "r"(a[1]), "r"(a[2]), "r"(a[3]), "r"(b[0]), "r"(b[1]));
}

// Split a float4 into bf16 hi/lo packed pairs.
__device__ __forceinline__ void split4(float4 v, uint2& h, uint2& l) {
    h.x = bf16pair(v.x, v.y);
    h.y = bf16pair(v.z, v.w);
    l.x = bf16pair(v.x - bf16rt(v.x), v.y - bf16rt(v.y));
    l.y = bf16pair(v.z - bf16rt(v.z), v.w - bf16rt(v.w));
}

// One 128x128x128 GEMM: acc += W(128x128) * X_tile(128 ch x 128 n), bf16 3-split.
__device__ __forceinline__ void run_gemm(
    const float* __restrict__ W, const float* __restrict__ X, size_t base,
    char* sm, uint32_t sb, int tid, int m0, int n0,
    uint32_t aLane, uint32_t bLane, float acc[2][4][4],
    float* sqp, float* Sp) {
    float* smf = (float*)sm;
    const int ja = tid >> 2, kq = tid & 3;
    const int nb = tid & 127, cg = tid >> 7;
    #pragma unroll 1
    for (int kc = 0; kc < 128; kc += 32) {
        __syncthreads();  // buffers free (prev mma done) / guards prior smem writers
        // ---- stage A (weights): [j][k] rows, pitch 80B, FULL 32-k chunk ----
        float4 w4a = __ldg((const float4*)(W + ja * 128 + kc) + kq);
        float4 w4b = __ldg((const float4*)(W + ja * 128 + kc) + kq + 4);
        {
            uint2 h, l;
            split4(w4a, h, l);
            *(uint2*)(sm + O_AH + ja * PBY + kq * 8) = h;
            *(uint2*)(sm + O_ALO + ja * PBY + kq * 8) = l;
            split4(w4b, h, l);
            *(uint2*)(sm + O_AH + ja * PBY + 32 + kq * 8) = h;
            *(uint2*)(sm + O_ALO + ja * PBY + 32 + kq * 8) = l;
        }
        // ---- stage B (pos/feat): transposed to [n][k] rows, pitch 80B ----
        float xv[8];
        #pragma unroll
        for (int cc = 0; cc < 8; cc++)
            xv[cc] = __ldg(X + base + (size_t)(kc + cg * 8 + cc) * 16384 + nb);
        if (sqp) {
            #pragma unroll
            for (int cc = 0; cc < 8; cc++) {
                *sqp = fmaf(smf[O_WQ / 4 + kc + cg * 8 + cc], xv[cc], *sqp);
                *Sp = fmaf(smf[O_WK / 4 + kc + cg * 8 + cc], xv[cc], *Sp);
            }
        }
        {
            uint4 h, l;
            h.x = bf16pair(xv[0], xv[1]);
            h.y = bf16pair(xv[2], xv[3]);
            h.z = bf16pair(xv[4], xv[5]);
            h.w = bf16pair(xv[6], xv[7]);
            l.x = bf16pair(xv[0] - bf16rt(xv[0]), xv[1] - bf16rt(xv[1]));
            l.y = bf16pair(xv[2] - bf16rt(xv[2]), xv[3] - bf16rt(xv[3]));
            l.z = bf16pair(xv[4] - bf16rt(xv[4]), xv[5] - bf16rt(xv[5]));
            l.w = bf16pair(xv[6] - bf16rt(xv[6]), xv[7] - bf16rt(xv[7]));
            *(uint4*)(sm + O_BH + nb * PBY + cg * 16) = h;
            *(uint4*)(sm + O_BL + nb * PBY + cg * 16) = l;
        }
        __syncthreads();
        // ---- mma: 3 split passes x 2 k16-steps ----
        #pragma unroll
        for (int p = 0; p < 3; p++) {
            const uint32_t aOff = (p == 2) ? O_ALO : O_AH;
            const uint32_t bOff = (p == 1) ? O_BL : O_BH;
            #pragma unroll
            for (int kk = 0; kk < 2; kk++) {
                uint32_t a0[4], a1[4], b0[4], b1[4];
                uint32_t aa = sb + aOff + aLane + kk * 32;
                uint32_t bb = sb + bOff + bLane + kk * 32;
                ldsm4(a0, aa + m0 * PBY);
                ldsm4(a1, aa + (m0 + 16) * PBY);
                ldsm4(b0, bb + n0 * PBY);
                ldsm4(b1, bb + (n0 + 16) * PBY);
                mma16(acc[0][0], a0, b0);
                mma16(acc[0][1], a0, b0 + 2);
                mma16(acc[0][2], a0, b1);
                mma16(acc[0][3], a0, b1 + 2);
                mma16(acc[1][0], a1, b0);
                mma16(acc[1][1], a1, b0 + 2);
                mma16(acc[1][2], a1, b1);
                mma16(acc[1][3], a1, b1 + 2);
            }
        }
    }
}

__global__ void __launch_bounds__(512, 1)
csa_kernel(const float* __restrict__ feat, const float* __restrict__ pos,
           const float* __restrict__ Wq, const float* __restrict__ Wk,
           const float* __restrict__ Wv, float* __restrict__ out) {
    extern __shared__ char sm[];
    float* smf = (float*)sm;
    const uint32_t sb = smem_u32(sm);
    const int tid = threadIdx.x;
    const int lane = tid & 31;
    const int m0 = (tid >> 7) * 32;       // warp row group
    const int n0 = ((tid >> 5) & 3) * 32; // warp col group
    const float NEG = __int_as_float(0xff800000);
    const float POS = __int_as_float(0x7f800000);

    // column sums of Wq and Wk (fp32)
    if (tid < 256) {
        const float* W = (tid < 128) ? Wq : Wk;
        const int c = tid & 127;
        float s0 = 0.f, s1 = 0.f, s2 = 0.f, s3 = 0.f;
        #pragma unroll 4
        for (int o = 0; o < 128; o += 4) {
            s0 += __ldg(W + (o + 0) * 128 + c);
            s1 += __ldg(W + (o + 1) * 128 + c);
            s2 += __ldg(W + (o + 2) * 128 + c);
            s3 += __ldg(W + (o + 3) * 128 + c);
        }
        smf[(tid < 128 ? O_WQ / 4 : O_WK / 4 - 128) + tid] = (s0 + s1) + (s2 + s3);
    }

    const size_t base =
        (size_t)blockIdx.y * (128u * 16384u) + (size_t)blockIdx.x * 128u;
    const uint32_t aLane =
        (uint32_t)((lane & 15) * PBY + (lane >> 4) * 16);
    const uint32_t bLane =
        (uint32_t)(((((lane >> 4) << 3) + (lane & 7)) * PBY) + (((lane >> 3) & 1) << 4));

    float acc[2][4][4];
    #pragma unroll
    for (int a = 0; a < 2; a++)
        #pragma unroll
        for (int b = 0; b < 4; b++)
            #pragma unroll
            for (int c = 0; c < 4; c++) acc[a][b][c] = 0.f;

    // ---------------- GEMM 1: K = Wk * pos ----------------
    float sqp = 0.f, Sp = 0.f;
    run_gemm(Wk, pos, base, sm, sb, tid, m0, n0, aLane, bLane, acc, &sqp, &Sp);

    // K epilogue -> sE; write sq/S partials
    float* sE = smf + O_SE / 4;
    #pragma unroll
    for (int mt = 0; mt < 2; mt++)
        #pragma unroll
        for (int nt = 0; nt < 4; nt++) {
            int r = m0 + mt * 16 + (lane >> 2);
            int col = n0 + nt * 8 + 2 * (lane & 3);
            *(float2*)(sE + r * SEP + col) =
                make_float2(acc[mt][nt][0], acc[mt][nt][1]);
            *(float2*)(sE + (r + 8) * SEP + col) =
                make_float2(acc[mt][nt][2], acc[mt][nt][3]);
        }
    smf[O_RED / 4 + tid] = sqp;
    smf[O_RED / 4 + 512 + tid] = Sp;
    __syncthreads();

    // partial max/min over j (4 threads per column)
    {
        const int n = tid & 127, q = tid >> 7;
        float mx = NEG, mn = POS;
        #pragma unroll 8
        for (int j = q * 32; j < q * 32 + 32; j++) {
            float v = sE[j * SEP + n];
            mx = fmaxf(mx, v);
            mn = fminf(mn, v);
        }
        smf[O_RED / 4 + 1024 + tid] = mx;
        smf[O_RED / 4 + 1536 + tid] = mn;
    }
    __syncthreads();
    if (tid < 128) {
        float sq = 0.f, S = 0.f, mx = NEG, mn = POS;
        #pragma unroll
        for (int g = 0; g < 4; g++) {
            sq += smf[O_RED / 4 + g * 128 + tid];
            S += smf[O_RED / 4 + 512 + g * 128 + tid];
            mx = fmaxf(mx, smf[O_RED / 4 + 1024 + g * 128 + tid]);
            mn = fminf(mn, smf[O_RED / 4 + 1536 + g * 128 + tid]);
        }
        float al = sq / (1e-9f + sq * S);
        smf[O_AL / 4 + tid] = al;
        smf[O_M / 4 + tid] = fmaxf(al * mx, al * mn);
    }
    __syncthreads();
    // exp pass
    {
        const int n = tid & 127, q = tid >> 7;
        float al = smf[O_AL / 4 + n], mval = smf[O_M / 4 + n];
        float d = 0.f;
        #pragma unroll 8
        for (int j = q * 32; j < q * 32 + 32; j++) {
            float e = __expf(fmaf(al, sE[j * SEP + n], -mval));
            sE[j * SEP + n] = e;
            d += e;
        }
        smf[O_RED / 4 + tid] = d;
    }
    __syncthreads();
    if (tid < 128) {
        float d = 0.f;
        #pragma unroll
        for (int g = 0; g < 4; g++) d += smf[O_RED / 4 + g * 128 + tid];
        smf[O_INV / 4 + tid] = 1.0f / d;
    }
    // (run_gemm's leading __syncthreads orders s_inv/sE before buffer reuse)

    // ---------------- GEMM 2: V = Wv * feat ----------------
    #pragma unroll
    for (int a = 0; a < 2; a++)
        #pragma unroll
        for (int b = 0; b < 4; b++)
            #pragma unroll
            for (int c = 0; c < 4; c++) acc[a][b][c] = 0.f;
    run_gemm(Wv, feat, base, sm, sb, tid, m0, n0, aLane, bLane, acc,
             nullptr, nullptr);

    // ---------------- apply: out = (e*inv)*V + feat ----------------
    const float* s_inv = smf + O_INV / 4;
    #pragma unroll
    for (int mt = 0; mt < 2; mt++)
        #pragma unroll
        for (int nt = 0; nt < 4; nt++) {
            int rr = m0 + mt * 16 + (lane >> 2);
            int col = n0 + nt * 8 + 2 * (lane & 3);
            float2 inv2 = *(const float2*)(s_inv + col);
            #pragma unroll
            for (int half = 0; half < 2; half++) {
                int r = rr + half * 8;
                float d0 = acc[mt][nt][2 * half];
                float d1 = acc[mt][nt][2 * half + 1];
                float2 e2 = *(const float2*)(sE + r * SEP + col);
                float2 f2 = __ldg((const float2*)(feat + base + (size_t)r * 16384 + col));
                float2 o;
                o.x = fmaf(e2.x * inv2.x, d0, f2.x);
                o.y = fmaf(e2.y * inv2.y, d1, f2.y);
                *(float2*)(out + base + (size_t)r * 16384 + col) = o;
            }
        }
}

extern "C" void kernel_launch(void* const* d_in, const int* in_sizes, int n_in,
                              void* d_out, int out_size) {
    const float* feat = (const float*)d_in[0];
    const float* pos  = (const float*)d_in[1];
    const float* Wq   = (const float*)d_in[2];
    const float* Wk   = (const float*)d_in[3];
    const float* Wv   = (const float*)d_in[4];
    float* out = (float*)d_out;

    cudaFuncSetAttribute(csa_kernel, cudaFuncAttributeMaxDynamicSharedMemorySize,
                         SMEM_BYTES);
    dim3 grid(16384 / 128, 16);
    csa_kernel<<<grid, 512, SMEM_BYTES>>>(feat, pos, Wq, Wk, Wv, out);
}

// round 8
// speedup vs baseline: 1.8531x; 1.8531x over previous
#include <cuda_runtime.h>
#include <cuda_bf16.h>
#include <cstdint>

#define PBY 80      // staged row pitch in bytes (40 bf16)
#define SEP 132     // sE pitch in f32

// smem offsets (bytes)
#define O_WQ 0
#define O_WK 512
#define O_AL 1024
#define O_M 1536
#define O_INV 2048
#define O_RED 2560        // 2048 f32 = 8192 B
#define O_AH 10752        // A hi  (128 x 40 bf16)
#define O_ALO 20992       // A lo
#define O_BH 31232        // B hi  (128 n-rows x 40 bf16)
#define O_BL 41472        // B lo
#define O_SE 51712        // 128 x 132 f32 = 67584
#define O_RAW 119296      // 2 x 16384 raw f32 B chunks (cp.async double buffer)
#define SMEM_BYTES 152064

__device__ __forceinline__ uint32_t smem_u32(const void* p) {
    uint32_t a;
    asm("{ .reg .u64 t; cvta.to.shared.u64 t, %1; cvt.u32.u64 %0, t; }"
        : "=r"(a) : "l"(p));
    return a;
}
__device__ __forceinline__ float bf16rt(float x) {
    return __bfloat162float(__float2bfloat16(x));
}
__device__ __forceinline__ uint32_t bf16pair(float lo, float hi) {
    __nv_bfloat162 t = __floats2bfloat162_rn(lo, hi);  // lo -> low half
    return *(uint32_t*)&t;
}
__device__ __forceinline__ void ldsm4(uint32_t* r, uint32_t addr) {
    asm volatile("ldmatrix.sync.aligned.m8n8.x4.shared.b16 {%0,%1,%2,%3}, [%4];"
                 : "=r"(r[0]), "=r"(r[1]), "=r"(r[2]), "=r"(r[3]) : "r"(addr));
}
__device__ __forceinline__ void mma16(float* d, const uint32_t* a, const uint32_t* b) {
    asm volatile(
        "mma.sync.aligned.m16n8k16.row.col.f32.bf16.bf16.f32 "
        "{%0,%1,%2,%3}, {%4,%5,%6,%7}, {%8,%9}, {%0,%1,%2,%3};"
        : "+f"(d[0]), "+f"(d[1]), "+f"(d[2]), "+f"(d[3])
        : "r"(a[0]), "r"(a[1]), "r"(a[2]), "r"(a[3]), "r"(b[0]), "r"(b[1]));
}
__device__ __forceinline__ void cp16(uint32_t dst, const float* src) {
    asm volatile("cp.async.cg.shared.global [%0], [%1], 16;"
                 :: "r"(dst), "l"(__cvta_generic_to_global(src)) : "memory");
}
__device__ __forceinline__ void split4(float4 v, uint2& h, uint2& l) {
    h.x = bf16pair(v.x, v.y);
    h.y = bf16pair(v.z, v.w);
    l.x = bf16pair(v.x - bf16rt(v.x), v.y - bf16rt(v.y));
    l.y = bf16pair(v.z - bf16rt(v.z), v.w - bf16rt(v.w));
}

// One 128x128x128 GEMM: acc += W(128x128) * X_tile(128 ch x 128 n).
// PASSES=3: bf16 3-split (hh + h*Bl + Al*h). PASSES=1: hi only.
template <int PASSES>
__device__ __forceinline__ void run_gemm(
    const float* __restrict__ W, const float* __restrict__ X, size_t base,
    char* sm, uint32_t sb, int tid, int m0, int n0,
    uint32_t aLane, uint32_t bLane, float acc[2][4][4],
    float* sqp, float* Sp) {
    float* smf = (float*)sm;
    const int ja = tid >> 2, kq = tid & 3;
    const int nb = tid & 127, cg = tid >> 7;

    // prologue: cp.async chunk 0 -> raw buffer 0
    #pragma unroll
    for (int s = 0; s < 2; s++) {
        int seg = tid + s * 512;
        int row = seg >> 5, c16 = seg & 31;
        cp16(sb + O_RAW + row * 512 + c16 * 16,
             X + base + (size_t)row * 16384 + c16 * 4);
    }
    asm volatile("cp.async.commit_group;" ::: "memory");

    #pragma unroll 1
    for (int kc4 = 0; kc4 < 4; kc4++) {
        const int kc = kc4 * 32;
        const int b = kc4 & 1;
        // A prefetch (L2-hot weights) — overlaps the wait below
        float4 w4a = __ldg((const float4*)(W + ja * 128 + kc) + kq);
        float4 w4b = __ldg((const float4*)(W + ja * 128 + kc) + kq + 4);
        if (kc4 < 3) {
            #pragma unroll
            for (int s = 0; s < 2; s++) {
                int seg = tid + s * 512;
                int row = seg >> 5, c16 = seg & 31;
                cp16(sb + O_RAW + (b ^ 1) * 16384 + row * 512 + c16 * 16,
                     X + base + (size_t)(kc + 32 + row) * 16384 + c16 * 4);
            }
            asm volatile("cp.async.commit_group;" ::: "memory");
            asm volatile("cp.async.wait_group 1;" ::: "memory");
        } else {
            asm volatile("cp.async.wait_group 0;" ::: "memory");
        }
        __syncthreads();  // prev mma done; raw chunk visible to all threads

        // ---- convert A: [j][k] rows, pitch 80B, full 32-k chunk ----
        {
            uint2 h, l;
            split4(w4a, h, l);
            *(uint2*)(sm + O_AH + ja * PBY + kq * 8) = h;
            if (PASSES == 3) *(uint2*)(sm + O_ALO + ja * PBY + kq * 8) = l;
            split4(w4b, h, l);
            *(uint2*)(sm + O_AH + ja * PBY + 32 + kq * 8) = h;
            if (PASSES == 3) *(uint2*)(sm + O_ALO + ja * PBY + 32 + kq * 8) = l;
        }
        // ---- convert B from raw smem: [n][k] rows, pitch 80B ----
        const float* raw = (const float*)(sm + O_RAW + b * 16384);
        float xv[8];
        #pragma unroll
        for (int cc = 0; cc < 8; cc++) xv[cc] = raw[(cg * 8 + cc) * 128 + nb];
        if (sqp) {
            #pragma unroll
            for (int cc = 0; cc < 8; cc++) {
                *sqp = fmaf(smf[O_WQ / 4 + kc + cg * 8 + cc], xv[cc], *sqp);
                *Sp = fmaf(smf[O_WK / 4 + kc + cg * 8 + cc], xv[cc], *Sp);
            }
        }
        {
            uint4 h;
            h.x = bf16pair(xv[0], xv[1]);
            h.y = bf16pair(xv[2], xv[3]);
            h.z = bf16pair(xv[4], xv[5]);
            h.w = bf16pair(xv[6], xv[7]);
            *(uint4*)(sm + O_BH + nb * PBY + cg * 16) = h;
            if (PASSES == 3) {
                uint4 l;
                l.x = bf16pair(xv[0] - bf16rt(xv[0]), xv[1] - bf16rt(xv[1]));
                l.y = bf16pair(xv[2] - bf16rt(xv[2]), xv[3] - bf16rt(xv[3]));
                l.z = bf16pair(xv[4] - bf16rt(xv[4]), xv[5] - bf16rt(xv[5]));
                l.w = bf16pair(xv[6] - bf16rt(xv[6]), xv[7] - bf16rt(xv[7]));
                *(uint4*)(sm + O_BL + nb * PBY + cg * 16) = l;
            }
        }
        __syncthreads();
        // ---- mma: PASSES split passes x 2 k16-steps (overlaps next cp DMA) ----
        #pragma unroll
        for (int p = 0; p < PASSES; p++) {
            const uint32_t aOff = (p == 2) ? O_ALO : O_AH;
            const uint32_t bOff = (p == 1) ? O_BL : O_BH;
            #pragma unroll
            for (int kk = 0; kk < 2; kk++) {
                uint32_t a0[4], a1[4], b0[4], b1[4];
                uint32_t aa = sb + aOff + aLane + kk * 32;
                uint32_t bb = sb + bOff + bLane + kk * 32;
                ldsm4(a0, aa + m0 * PBY);
                ldsm4(a1, aa + (m0 + 16) * PBY);
                ldsm4(b0, bb + n0 * PBY);
                ldsm4(b1, bb + (n0 + 16) * PBY);
                mma16(acc[0][0], a0, b0);
                mma16(acc[0][1], a0, b0 + 2);
                mma16(acc[0][2], a0, b1);
                mma16(acc[0][3], a0, b1 + 2);
                mma16(acc[1][0], a1, b0);
                mma16(acc[1][1], a1, b0 + 2);
                mma16(acc[1][2], a1, b1);
                mma16(acc[1][3], a1, b1 + 2);
            }
        }
    }
}

__global__ void __launch_bounds__(512, 1)
csa_kernel(const float* __restrict__ feat, const float* __restrict__ pos,
           const float* __restrict__ Wq, const float* __restrict__ Wk,
           const float* __restrict__ Wv, float* __restrict__ out) {
    extern __shared__ char sm[];
    float* smf = (float*)sm;
    const uint32_t sb = smem_u32(sm);
    const int tid = threadIdx.x;
    const int lane = tid & 31;
    const int m0 = (tid >> 7) * 32;       // warp row group
    const int n0 = ((tid >> 5) & 3) * 32; // warp col group
    const float NEG = __int_as_float(0xff800000);
    const float POS = __int_as_float(0x7f800000);

    // column sums of Wq and Wk (fp32)
    if (tid < 256) {
        const float* W = (tid < 128) ? Wq : Wk;
        const int c = tid & 127;
        float s0 = 0.f, s1 = 0.f, s2 = 0.f, s3 = 0.f;
        #pragma unroll 4
        for (int o = 0; o < 128; o += 4) {
            s0 += __ldg(W + (o + 0) * 128 + c);
            s1 += __ldg(W + (o + 1) * 128 + c);
            s2 += __ldg(W + (o + 2) * 128 + c);
            s3 += __ldg(W + (o + 3) * 128 + c);
        }
        smf[(tid < 128 ? O_WQ / 4 : O_WK / 4 - 128) + tid] = (s0 + s1) + (s2 + s3);
    }

    const size_t base =
        (size_t)blockIdx.y * (128u * 16384u) + (size_t)blockIdx.x * 128u;
    const uint32_t aLane =
        (uint32_t)((lane & 15) * PBY + (lane >> 4) * 16);
    const uint32_t bLane =
        (uint32_t)(((((lane >> 4) << 3) + (lane & 7)) * PBY) + (((lane >> 3) & 1) << 4));

    float acc[2][4][4];
    #pragma unroll
    for (int a = 0; a < 2; a++)
        #pragma unroll
        for (int b = 0; b < 4; b++)
            #pragma unroll
            for (int c = 0; c < 4; c++) acc[a][b][c] = 0.f;

    // ---------------- GEMM 1: K = Wk * pos (3-pass split) ----------------
    float sqp = 0.f, Sp = 0.f;
    run_gemm<3>(Wk, pos, base, sm, sb, tid, m0, n0, aLane, bLane, acc, &sqp, &Sp);

    // K epilogue -> sE; write sq/S partials
    float* sE = smf + O_SE / 4;
    #pragma unroll
    for (int mt = 0; mt < 2; mt++)
        #pragma unroll
        for (int nt = 0; nt < 4; nt++) {
            int r = m0 + mt * 16 + (lane >> 2);
            int col = n0 + nt * 8 + 2 * (lane & 3);
            *(float2*)(sE + r * SEP + col) =
                make_float2(acc[mt][nt][0], acc[mt][nt][1]);
            *(float2*)(sE + (r + 8) * SEP + col) =
                make_float2(acc[mt][nt][2], acc[mt][nt][3]);
        }
    smf[O_RED / 4 + tid] = sqp;
    smf[O_RED / 4 + 512 + tid] = Sp;
    __syncthreads();

    // partial max/min over j (4 threads per column)
    {
        const int n = tid & 127, q = tid >> 7;
        float mx = NEG, mn = POS;
        #pragma unroll 8
        for (int j = q * 32; j < q * 32 + 32; j++) {
            float v = sE[j * SEP + n];
            mx = fmaxf(mx, v);
            mn = fminf(mn, v);
        }
        smf[O_RED / 4 + 1024 + tid] = mx;
        smf[O_RED / 4 + 1536 + tid] = mn;
    }
    __syncthreads();
    if (tid < 128) {
        float sq = 0.f, S = 0.f, mx = NEG, mn = POS;
        #pragma unroll
        for (int g = 0; g < 4; g++) {
            sq += smf[O_RED / 4 + g * 128 + tid];
            S += smf[O_RED / 4 + 512 + g * 128 + tid];
            mx = fmaxf(mx, smf[O_RED / 4 + 1024 + g * 128 + tid]);
            mn = fminf(mn, smf[O_RED / 4 + 1536 + g * 128 + tid]);
        }
        float al = sq / (1e-9f + sq * S);
        smf[O_AL / 4 + tid] = al;
        smf[O_M / 4 + tid] = fmaxf(al * mx, al * mn);
    }
    __syncthreads();
    // exp pass
    {
        const int n = tid & 127, q = tid >> 7;
        float al = smf[O_AL / 4 + n], mval = smf[O_M / 4 + n];
        float d = 0.f;
        #pragma unroll 8
        for (int j = q * 32; j < q * 32 + 32; j++) {
            float e = __expf(fmaf(al, sE[j * SEP + n], -mval));
            sE[j * SEP + n] = e;
            d += e;
        }
        smf[O_RED / 4 + tid] = d;
    }
    __syncthreads();
    if (tid < 128) {
        float d = 0.f;
        #pragma unroll
        for (int g = 0; g < 4; g++) d += smf[O_RED / 4 + g * 128 + tid];
        smf[O_INV / 4 + tid] = 1.0f / d;
    }
    // (run_gemm's first in-loop __syncthreads orders s_inv/sE before buffer reuse)

    // ---------------- GEMM 2: V = Wv * feat (1-pass, bf16 hi) ----------------
    #pragma unroll
    for (int a = 0; a < 2; a++)
        #pragma unroll
        for (int b = 0; b < 4; b++)
            #pragma unroll
            for (int c = 0; c < 4; c++) acc[a][b][c] = 0.f;
    run_gemm<1>(Wv, feat, base, sm, sb, tid, m0, n0, aLane, bLane, acc,
                nullptr, nullptr);

    // ---------------- apply: out = (e*inv)*V + feat ----------------
    const float* s_inv = smf + O_INV / 4;
    #pragma unroll
    for (int mt = 0; mt < 2; mt++)
        #pragma unroll
        for (int nt = 0; nt < 4; nt++) {
            int rr = m0 + mt * 16 + (lane >> 2);
            int col = n0 + nt * 8 + 2 * (lane & 3);
            float2 inv2 = *(const float2*)(s_inv + col);
            #pragma unroll
            for (int half = 0; half < 2; half++) {
                int r = rr + half * 8;
                float d0 = acc[mt][nt][2 * half];
                float d1 = acc[mt][nt][2 * half + 1];
                float2 e2 = *(const float2*)(sE + r * SEP + col);
                float2 f2 = __ldg((const float2*)(feat + base + (size_t)r * 16384 + col));
                float2 o;
                o.x = fmaf(e2.x * inv2.x, d0, f2.x);
                o.y = fmaf(e2.y * inv2.y, d1, f2.y);
                *(float2*)(out + base + (size_t)r * 16384 + col) = o;
            }
        }
}

extern "C" void kernel_launch(void* const* d_in, const int* in_sizes, int n_in,
                              void* d_out, int out_size) {
    const float* feat = (const float*)d_in[0];
    const float* pos  = (const float*)d_in[1];
    const float* Wq   = (const float*)d_in[2];
    const float* Wk   = (const float*)d_in[3];
    const float* Wv   = (const float*)d_in[4];
    float* out = (float*)d_out;

    cudaFuncSetAttribute(csa_kernel, cudaFuncAttributeMaxDynamicSharedMemorySize,
                         SMEM_BYTES);
    dim3 grid(16384 / 128, 16);
    csa_kernel<<<grid, 512, SMEM_BYTES>>>(feat, pos, Wq, Wk, Wv, out);
}

// round 9
// speedup vs baseline: 2.0613x; 1.1123x over previous
#include <cuda_runtime.h>
#include <cuda_bf16.h>
#include <cstdint>

#define PBY 80      // staged row pitch bytes (40 bf16)
#define SEP 68      // sE pitch in f32

// smem offsets (bytes)
#define O_WQ 0            // 128 f
#define O_WK 512          // 128 f
#define O_AL 1024         // 64 f
#define O_M 1280          // 64 f
#define O_INV 1536        // 64 f
#define O_RED 1792        // 1024 f = 4096 B -> 5888
#define O_AH 6144         // 2 x 128x80 = 20480
#define O_ALO 26624       // 2 x 10240
#define O_BH 47104        // 64 x 80 = 5120
#define O_BL 52224        // 5120
#define O_RAW 57344       // 2 x 8192 raw f32 B chunks
#define O_SE 73728        // 128 x 68 f = 34816
#define SMEM_BYTES 108544 // x2 CTAs = 217088 <= 228KB/SM

// Pre-split weights (bf16 hi/lo), laid out per 32-k chunk in the exact smem
// row image (64 B = 32 bf16 per row) so staging is a straight cp.async.
__device__ __align__(16) uint2 g_wk_hi[4][128][8];
__device__ __align__(16) uint2 g_wk_lo[4][128][8];
__device__ __align__(16) uint2 g_wv_hi[4][128][8];

__device__ __forceinline__ uint32_t smem_u32(const void* p) {
    uint32_t a;
    asm("{ .reg .u64 t; cvta.to.shared.u64 t, %1; cvt.u32.u64 %0, t; }"
        : "=r"(a) : "l"(p));
    return a;
}
__device__ __forceinline__ float bf16rt(float x) {
    return __bfloat162float(__float2bfloat16(x));
}
__device__ __forceinline__ uint32_t bf16pair(float lo, float hi) {
    __nv_bfloat162 t = __floats2bfloat162_rn(lo, hi);
    return *(uint32_t*)&t;
}
__device__ __forceinline__ void split4(float4 v, uint2& h, uint2& l) {
    h.x = bf16pair(v.x, v.y);
    h.y = bf16pair(v.z, v.w);
    l.x = bf16pair(v.x - bf16rt(v.x), v.y - bf16rt(v.y));
    l.y = bf16pair(v.z - bf16rt(v.z), v.w - bf16rt(v.w));
}
__device__ __forceinline__ void ldsm4(uint32_t* r, uint32_t addr) {
    asm volatile("ldmatrix.sync.aligned.m8n8.x4.shared.b16 {%0,%1,%2,%3}, [%4];"
                 : "=r"(r[0]), "=r"(r[1]), "=r"(r[2]), "=r"(r[3]) : "r"(addr));
}
__device__ __forceinline__ void mma16(float* d, const uint32_t* a, const uint32_t* b) {
    asm volatile(
        "mma.sync.aligned.m16n8k16.row.col.f32.bf16.bf16.f32 "
        "{%0,%1,%2,%3}, {%4,%5,%6,%7}, {%8,%9}, {%0,%1,%2,%3};"
        : "+f"(d[0]), "+f"(d[1]), "+f"(d[2]), "+f"(d[3])
        : "r"(a[0]), "r"(a[1]), "r"(a[2]), "r"(a[3]), "r"(b[0]), "r"(b[1]));
}
__device__ __forceinline__ void cp16(uint32_t dst, const float* src) {
    asm volatile("cp.async.cg.shared.global [%0], [%1], 16;"
                 :: "r"(dst), "l"(__cvta_generic_to_global(src)) : "memory");
}
#define CP_COMMIT() asm volatile("cp.async.commit_group;" ::: "memory")
#define CP_WAIT(n) asm volatile("cp.async.wait_group %0;" :: "n"(n) : "memory")

// ---------------- prep: split Wk (hi+lo) and Wv (hi) once ----------------
__global__ void prep_kernel(const float* __restrict__ Wk,
                            const float* __restrict__ Wv) {
    const int c = blockIdx.x;          // k-chunk
    const int j = threadIdx.x >> 2, kq = threadIdx.x & 3;
    const int kc = c * 32;
    uint2 h, l;
    float4 a = __ldg((const float4*)(Wk + j * 128 + kc) + kq);
    float4 b = __ldg((const float4*)(Wk + j * 128 + kc) + kq + 4);
    split4(a, h, l);
    g_wk_hi[c][j][kq] = h;
    g_wk_lo[c][j][kq] = l;
    split4(b, h, l);
    g_wk_hi[c][j][4 + kq] = h;
    g_wk_lo[c][j][4 + kq] = l;
    a = __ldg((const float4*)(Wv + j * 128 + kc) + kq);
    b = __ldg((const float4*)(Wv + j * 128 + kc) + kq + 4);
    split4(a, h, l);
    g_wv_hi[c][j][kq] = h;
    split4(b, h, l);
    g_wv_hi[c][j][4 + kq] = h;
}

// DMA one k-chunk: prepped A image(s) + raw B tile (32 ch x 64 n).
template <int PASSES>
__device__ __forceinline__ void dma_chunk(uint32_t sb, int chunk, int buf,
                                          const float* __restrict__ X,
                                          size_t base, int tid) {
    #pragma unroll
    for (int s = 0; s < 2; s++) {
        int seg = tid + s * 256;
        int row = seg >> 2, s16 = seg & 3;
        const float* hsrc =
            (const float*)(PASSES == 3 ? g_wk_hi[chunk][row] : g_wv_hi[chunk][row]);
        cp16(sb + O_AH + buf * 10240 + row * PBY + s16 * 16, hsrc + s16 * 4);
        if (PASSES == 3)
            cp16(sb + O_ALO + buf * 10240 + row * PBY + s16 * 16,
                 (const float*)g_wk_lo[chunk][row] + s16 * 4);
    }
    #pragma unroll
    for (int s = 0; s < 2; s++) {
        int seg = tid + s * 256;
        int row = seg >> 4, c16 = seg & 15;
        cp16(sb + O_RAW + buf * 8192 + row * 256 + c16 * 16,
             X + base + (size_t)(chunk * 32 + row) * 16384 + c16 * 4);
    }
}

// 128x64x128 GEMM, A from prepped globals, bf16 split (3-pass or 1-pass).
template <int PASSES>
__device__ __forceinline__ void run_gemm(
    const float* __restrict__ X, size_t base, char* sm, uint32_t sb, int tid,
    int m0, int n0, uint32_t aLane, uint32_t bLane, float acc[2][4][4],
    float* sqp, float* Sp) {
    float* smf = (float*)sm;
    const int nb = tid & 63, cg = tid >> 6;

    dma_chunk<PASSES>(sb, 0, 0, X, base, tid);
    CP_COMMIT();
    #pragma unroll 1
    for (int ch = 0; ch < 4; ch++) {
        const int b = ch & 1;
        if (ch < 3) {
            dma_chunk<PASSES>(sb, ch + 1, b ^ 1, X, base, tid);
            CP_COMMIT();
            CP_WAIT(1);
        } else {
            CP_WAIT(0);
        }
        __syncthreads();  // chunk data visible; prev mma done with BH/BL

        // ---- convert B (raw f32 -> bf16 hi/lo), plus sq/S partials ----
        const float* raw = (const float*)(sm + O_RAW + b * 8192);
        float xv[8];
        #pragma unroll
        for (int cc = 0; cc < 8; cc++) xv[cc] = raw[(cg * 8 + cc) * 64 + nb];
        if (sqp) {
            #pragma unroll
            for (int cc = 0; cc < 8; cc++) {
                *sqp = fmaf(smf[O_WQ / 4 + ch * 32 + cg * 8 + cc], xv[cc], *sqp);
                *Sp = fmaf(smf[O_WK / 4 + ch * 32 + cg * 8 + cc], xv[cc], *Sp);
            }
        }
        {
            uint4 h;
            h.x = bf16pair(xv[0], xv[1]);
            h.y = bf16pair(xv[2], xv[3]);
            h.z = bf16pair(xv[4], xv[5]);
            h.w = bf16pair(xv[6], xv[7]);
            *(uint4*)(sm + O_BH + nb * PBY + cg * 16) = h;
            if (PASSES == 3) {
                uint4 l;
                l.x = bf16pair(xv[0] - bf16rt(xv[0]), xv[1] - bf16rt(xv[1]));
                l.y = bf16pair(xv[2] - bf16rt(xv[2]), xv[3] - bf16rt(xv[3]));
                l.z = bf16pair(xv[4] - bf16rt(xv[4]), xv[5] - bf16rt(xv[5]));
                l.w = bf16pair(xv[6] - bf16rt(xv[6]), xv[7] - bf16rt(xv[7]));
                *(uint4*)(sm + O_BL + nb * PBY + cg * 16) = l;
            }
        }
        __syncthreads();

        // ---- mma: PASSES x 2 k16-steps (overlaps next chunk's DMA) ----
        #pragma unroll
        for (int p = 0; p < PASSES; p++) {
            const uint32_t aOff = ((p == 2) ? O_ALO : O_AH) + b * 10240;
            const uint32_t bOff = (p == 1) ? O_BL : O_BH;
            #pragma unroll
            for (int kk = 0; kk < 2; kk++) {
                uint32_t a0[4], a1[4], b0[4], b1[4];
                uint32_t aa = sb + aOff + aLane + kk * 32;
                uint32_t bb = sb + bOff + bLane + kk * 32;
                ldsm4(a0, aa + m0 * PBY);
                ldsm4(a1, aa + (m0 + 16) * PBY);
                ldsm4(b0, bb + n0 * PBY);
                ldsm4(b1, bb + (n0 + 16) * PBY);
                mma16(acc[0][0], a0, b0);
                mma16(acc[0][1], a0, b0 + 2);
                mma16(acc[0][2], a0, b1);
                mma16(acc[0][3], a0, b1 + 2);
                mma16(acc[1][0], a1, b0);
                mma16(acc[1][1], a1, b0 + 2);
                mma16(acc[1][2], a1, b1);
                mme_dummy:;
                mma16(acc[1][3], a1, b1 + 2);
            }
        }
    }
}

__global__ void __launch_bounds__(256, 2)
csa_kernel(const float* __restrict__ feat, const float* __restrict__ pos,
           const float* __restrict__ Wq, const float* __restrict__ Wk,
           const float* __restrict__ Wv, float* __restrict__ out) {
    extern __shared__ char sm[];
    float* smf = (float*)sm;
    const uint32_t sb = smem_u32(sm);
    const int tid = threadIdx.x;
    const int lane = tid & 31;
    const int wid = tid >> 5;
    const int m0 = (wid >> 1) * 32;   // 4 row groups
    const int n0 = (wid & 1) * 32;    // 2 col groups
    const float NEG = __int_as_float(0xff800000);
    const float POS = __int_as_float(0x7f800000);
    const int R = O_RED / 4;

    // column sums of Wq (tid<128) and Wk (tid>=128), fp32
    {
        const float* W = (tid < 128) ? Wq : Wk;
        const int c = tid & 127;
        float s0 = 0.f, s1 = 0.f, s2 = 0.f, s3 = 0.f;
        #pragma unroll 4
        for (int o = 0; o < 128; o += 4) {
            s0 += __ldg(W + (o + 0) * 128 + c);
            s1 += __ldg(W + (o + 1) * 128 + c);
            s2 += __ldg(W + (o + 2) * 128 + c);
            s3 += __ldg(W + (o + 3) * 128 + c);
        }
        smf[(tid < 128 ? O_WQ / 4 : O_WK / 4 - 128) + tid] = (s0 + s1) + (s2 + s3);
    }
    __syncthreads();

    const size_t base =
        (size_t)blockIdx.y * (128u * 16384u) + (size_t)blockIdx.x * 64u;
    const uint32_t aLane = (uint32_t)((lane & 15) * PBY + (lane >> 4) * 16);
    const uint32_t bLane =
        (uint32_t)(((((lane >> 4) << 3) + (lane & 7)) * PBY) + (((lane >> 3) & 1) << 4));

    float acc[2][4][4];
    #pragma unroll
    for (int a = 0; a < 2; a++)
        #pragma unroll
        for (int b = 0; b < 4; b++)
            #pragma unroll
            for (int c = 0; c < 4; c++) acc[a][b][c] = 0.f;

    // ---------------- GEMM 1: K = Wk * pos (3-pass split) ----------------
    float sqp = 0.f, Sp = 0.f;
    run_gemm<3>(pos, base, sm, sb, tid, m0, n0, aLane, bLane, acc, &sqp, &Sp);

    // K epilogue -> sE; sq/S partials
    float* sE = smf + O_SE / 4;
    #pragma unroll
    for (int mt = 0; mt < 2; mt++)
        #pragma unroll
        for (int nt = 0; nt < 4; nt++) {
            int r = m0 + mt * 16 + (lane >> 2);
            int col = n0 + nt * 8 + 2 * (lane & 3);
            *(float2*)(sE + r * SEP + col) =
                make_float2(acc[mt][nt][0], acc[mt][nt][1]);
            *(float2*)(sE + (r + 8) * SEP + col) =
                make_float2(acc[mt][nt][2], acc[mt][nt][3]);
        }
    smf[R + tid] = sqp;
    smf[R + 256 + tid] = Sp;
    __syncthreads();

    // mx/mn partials (4 thread-groups per column); tid<64 computes al
    {
        const int n = tid & 63, q = tid >> 6;
        float mx = NEG, mn = POS;
        #pragma unroll 8
        for (int j = q * 32; j < q * 32 + 32; j++) {
            float v = sE[j * SEP + n];
            mx = fmaxf(mx, v);
            mn = fminf(mn, v);
        }
        smf[R + 512 + tid] = mx;
        smf[R + 768 + tid] = mn;
        if (tid < 64) {
            float sq = 0.f, S = 0.f;
            #pragma unroll
            for (int g = 0; g < 4; g++) {
                sq += smf[R + g * 64 + n];
                S += smf[R + 256 + g * 64 + n];
            }
            smf[O_AL / 4 + n] = sq / (1e-9f + sq * S);
        }
    }
    __syncthreads();
    if (tid < 64) {
        float mx = NEG, mn = POS;
        #pragma unroll
        for (int g = 0; g < 4; g++) {
            mx = fmaxf(mx, smf[R + 512 + g * 64 + tid]);
            mn = fminf(mn, smf[R + 768 + g * 64 + tid]);
        }
        float al = smf[O_AL / 4 + tid];
        smf[O_M / 4 + tid] = fmaxf(al * mx, al * mn);
    }
    __syncthreads();
    // exp pass
    {
        const int n = tid & 63, q = tid >> 6;
        float al = smf[O_AL / 4 + n], mval = smf[O_M / 4 + n];
        float d = 0.f;
        #pragma unroll 8
        for (int j = q * 32; j < q * 32 + 32; j++) {
            float e = __expf(fmaf(al, sE[j * SEP + n], -mval));
            sE[j * SEP + n] = e;
            d += e;
        }
        smf[R + tid] = d;
    }
    __syncthreads();
    if (tid < 64) {
        float d = 0.f;
        #pragma unroll
        for (int g = 0; g < 4; g++) d += smf[R + g * 64 + tid];
        smf[O_INV / 4 + tid] = 1.0f / d;
    }
    // (run_gemm's first in-loop sync orders s_inv before later readers)

    // ---------------- GEMM 2: V = Wv * feat (1-pass hi) ----------------
    #pragma unroll
    for (int a = 0; a < 2; a++)
        #pragma unroll
        for (int b = 0; b < 4; b++)
            #pragma unroll
            for (int c = 0; c < 4; c++) acc[a][b][c] = 0.f;
    run_gemm<1>(feat, base, sm, sb, tid, m0, n0, aLane, bLane, acc,
                nullptr, nullptr);

    // ---------------- apply: out = (e*inv)*V + feat ----------------
    const float* s_inv = smf + O_INV / 4;
    #pragma unroll
    for (int mt = 0; mt < 2; mt++)
        #pragma unroll
        for (int nt = 0; nt < 4; nt++) {
            int rr = m0 + mt * 16 + (lane >> 2);
            int col = n0 + nt * 8 + 2 * (lane & 3);
            float2 inv2 = *(const float2*)(s_inv + col);
            #pragma unroll
            for (int half = 0; half < 2; half++) {
                int r = rr + half * 8;
                float d0 = acc[mt][nt][2 * half];
                float d1 = acc[mt][nt][2 * half + 1];
                float2 e2 = *(const float2*)(sE + r * SEP + col);
                float2 f2 =
                    __ldg((const float2*)(feat + base + (size_t)r * 16384 + col));
                float2 o;
                o.x = fmaf(e2.x * inv2.x, d0, f2.x);
                o.y = fmaf(e2.y * inv2.y, d1, f2.y);
                *(float2*)(out + base + (size_t)r * 16384 + col) = o;
            }
        }
}

extern "C" void kernel_launch(void* const* d_in, const int* in_sizes, int n_in,
                              void* d_out, int out_size) {
    const float* feat = (const float*)d_in[0];
    const float* pos  = (const float*)d_in[1];
    const float* Wq   = (const float*)d_in[2];
    const float* Wk   = (const float*)d_in[3];
    const float* Wv   = (const float*)d_in[4];
    float* out = (float*)d_out;

    prep_kernel<<<4, 512>>>(Wk, Wv);
    cudaFuncSetAttribute(csa_kernel, cudaFuncAttributeMaxDynamicSharedMemorySize,
                         SMEM_BYTES);
    dim3 grid(16384 / 64, 16);
    csa_kernel<<<grid, 256, SMEM_BYTES>>>(feat, pos, Wq, Wk, Wv, out);
}

// round 10
// speedup vs baseline: 2.1000x; 1.0188x over previous
#include <cuda_runtime.h>
#include <cuda_bf16.h>
#include <cstdint>

#define PBY 80      // staged row pitch bytes (40 bf16)
#define SEP 68      // sE pitch in f32

// smem offsets (bytes)
#define O_WQ 0            // 128 f
#define O_WK 512          // 128 f
#define O_AL 1024         // 64 f
#define O_M 1280          // 64 f
#define O_INV 1536        // 64 f
#define O_RED 1792        // 1024 f = 4096 B -> 5888
#define O_AH 6144         // 2 x 128x80 = 20480
#define O_ALO 26624       // 2 x 10240
#define O_BH 47104        // 64 x 80 = 5120
#define O_BL 52224        // 5120
#define O_RAW 57344       // 2 x 8192 raw f32 B chunks
#define O_SE 73728        // 128 x 68 f = 34816
#define SMEM_BYTES 108544 // x2 CTAs = 217088 <= 228KB/SM

// Pre-split weights (bf16 hi/lo) in the exact smem row image (cp.async-able).
__device__ __align__(16) uint2 g_wk_hi[4][128][8];
__device__ __align__(16) uint2 g_wk_lo[4][128][8];
__device__ __align__(16) uint2 g_wv_hi[4][128][8];

__device__ __forceinline__ uint32_t smem_u32(const void* p) {
    uint32_t a;
    asm("{ .reg .u64 t; cvta.to.shared.u64 t, %1; cvt.u32.u64 %0, t; }"
        : "=r"(a) : "l"(p));
    return a;
}
__device__ __forceinline__ float bf16rt(float x) {
    return __bfloat162float(__float2bfloat16(x));
}
__device__ __forceinline__ uint32_t bf16pair(float lo, float hi) {
    __nv_bfloat162 t = __floats2bfloat162_rn(lo, hi);
    return *(uint32_t*)&t;
}
__device__ __forceinline__ void split4(float4 v, uint2& h, uint2& l) {
    h.x = bf16pair(v.x, v.y);
    h.y = bf16pair(v.z, v.w);
    l.x = bf16pair(v.x - bf16rt(v.x), v.y - bf16rt(v.y));
    l.y = bf16pair(v.z - bf16rt(v.z), v.w - bf16rt(v.w));
}
__device__ __forceinline__ void ldsm4(uint32_t* r, uint32_t addr) {
    asm volatile("ldmatrix.sync.aligned.m8n8.x4.shared.b16 {%0,%1,%2,%3}, [%4];"
                 : "=r"(r[0]), "=r"(r[1]), "=r"(r[2]), "=r"(r[3]) : "r"(addr));
}
__device__ __forceinline__ void mma16(float* d, const uint32_t* a, const uint32_t* b) {
    asm volatile(
        "mma.sync.aligned.m16n8k16.row.col.f32.bf16.bf16.f32 "
        "{%0,%1,%2,%3}, {%4,%5,%6,%7}, {%8,%9}, {%0,%1,%2,%3};"
        : "+f"(d[0]), "+f"(d[1]), "+f"(d[2]), "+f"(d[3])
        : "r"(a[0]), "r"(a[1]), "r"(a[2]), "r"(a[3]), "r"(b[0]), "r"(b[1]));
}
__device__ __forceinline__ void mma8x(float acc[2][4][4], const uint32_t* a0,
                                      const uint32_t* a1, const uint32_t* b0,
                                      const uint32_t* b1) {
    mma16(acc[0][0], a0, b0);
    mma16(acc[0][1], a0, b0 + 2);
    mma16(acc[0][2], a0, b1);
    mma16(acc[0][3], a0, b1 + 2);
    mma16(acc[1][0], a1, b0);
    mma16(acc[1][1], a1, b0 + 2);
    mma16(acc[1][2], a1, b1);
    mma16(acc[1][3], a1, b1 + 2);
}
__device__ __forceinline__ void cp16(uint32_t dst, const float* src) {
    asm volatile("cp.async.cg.shared.global [%0], [%1], 16;"
                 :: "r"(dst), "l"(__cvta_generic_to_global(src)) : "memory");
}
#define CP_COMMIT() asm volatile("cp.async.commit_group;" ::: "memory")
#define CP_WAIT(n) asm volatile("cp.async.wait_group %0;" :: "n"(n) : "memory")

// ---------------- prep: split Wk (hi+lo) and Wv (hi) once ----------------
__global__ void prep_kernel(const float* __restrict__ Wk,
                            const float* __restrict__ Wv) {
    const int c = blockIdx.x;
    const int j = threadIdx.x >> 2, kq = threadIdx.x & 3;
    const int kc = c * 32;
    uint2 h, l;
    float4 a = __ldg((const float4*)(Wk + j * 128 + kc) + kq);
    float4 b = __ldg((const float4*)(Wk + j * 128 + kc) + kq + 4);
    split4(a, h, l);
    g_wk_hi[c][j][kq] = h;
    g_wk_lo[c][j][kq] = l;
    split4(b, h, l);
    g_wk_hi[c][j][4 + kq] = h;
    g_wk_lo[c][j][4 + kq] = l;
    a = __ldg((const float4*)(Wv + j * 128 + kc) + kq);
    b = __ldg((const float4*)(Wv + j * 128 + kc) + kq + 4);
    split4(a, h, l);
    g_wv_hi[c][j][kq] = h;
    split4(b, h, l);
    g_wv_hi[c][j][4 + kq] = h;
}

template <int PASSES>
__device__ __forceinline__ void dma_chunk(uint32_t sb, int chunk, int buf,
                                          const float* __restrict__ X,
                                          size_t base, int tid) {
    #pragma unroll
    for (int s = 0; s < 2; s++) {
        int seg = tid + s * 256;
        int row = seg >> 2, s16 = seg & 3;
        const float* hsrc =
            (const float*)(PASSES == 3 ? g_wk_hi[chunk][row] : g_wv_hi[chunk][row]);
        cp16(sb + O_AH + buf * 10240 + row * PBY + s16 * 16, hsrc + s16 * 4);
        if (PASSES == 3)
            cp16(sb + O_ALO + buf * 10240 + row * PBY + s16 * 16,
                 (const float*)g_wk_lo[chunk][row] + s16 * 4);
    }
    #pragma unroll
    for (int s = 0; s < 2; s++) {
        int seg = tid + s * 256;
        int row = seg >> 4, c16 = seg & 15;
        cp16(sb + O_RAW + buf * 8192 + row * 256 + c16 * 16,
             X + base + (size_t)(chunk * 32 + row) * 16384 + c16 * 4);
    }
}

// 128x64x128 GEMM. PASSES=3: bf16 split hh+hl+lh with fragment reuse.
template <int PASSES, bool PROLOGUE>
__device__ __forceinline__ void run_gemm(
    const float* __restrict__ X, size_t base, char* sm, uint32_t sb, int tid,
    int m0, int n0, uint32_t aLane, uint32_t bLane, float acc[2][4][4],
    float* sqp, float* Sp) {
    float* smf = (float*)sm;
    const int nb = tid & 63, cg = tid >> 6;

    if (PROLOGUE) {
        dma_chunk<PASSES>(sb, 0, 0, X, base, tid);
        CP_COMMIT();
    }
    #pragma unroll 1
    for (int ch = 0; ch < 4; ch++) {
        const int b = ch & 1;
        if (ch < 3) {
            dma_chunk<PASSES>(sb, ch + 1, b ^ 1, X, base, tid);
            CP_COMMIT();
            CP_WAIT(1);
        } else {
            CP_WAIT(0);
        }
        __syncthreads();  // chunk data visible; prev mma done with BH/BL

        // ---- convert B (raw f32 -> bf16 hi/lo), plus sq/S partials ----
        const float* raw = (const float*)(sm + O_RAW + b * 8192);
        float xv[8];
        #pragma unroll
        for (int cc = 0; cc < 8; cc++) xv[cc] = raw[(cg * 8 + cc) * 64 + nb];
        if (sqp) {
            #pragma unroll
            for (int cc = 0; cc < 8; cc++) {
                *sqp = fmaf(smf[O_WQ / 4 + ch * 32 + cg * 8 + cc], xv[cc], *sqp);
                *Sp = fmaf(smf[O_WK / 4 + ch * 32 + cg * 8 + cc], xv[cc], *Sp);
            }
        }
        {
            uint4 h;
            h.x = bf16pair(xv[0], xv[1]);
            h.y = bf16pair(xv[2], xv[3]);
            h.z = bf16pair(xv[4], xv[5]);
            h.w = bf16pair(xv[6], xv[7]);
            *(uint4*)(sm + O_BH + nb * PBY + cg * 16) = h;
            if (PASSES == 3) {
                uint4 l;
                l.x = bf16pair(xv[0] - bf16rt(xv[0]), xv[1] - bf16rt(xv[1]));
                l.y = bf16pair(xv[2] - bf16rt(xv[2]), xv[3] - bf16rt(xv[3]));
                l.z = bf16pair(xv[4] - bf16rt(xv[4]), xv[5] - bf16rt(xv[5]));
                l.w = bf16pair(xv[6] - bf16rt(xv[6]), xv[7] - bf16rt(xv[7]));
                *(uint4*)(sm + O_BL + nb * PBY + cg * 16) = l;
            }
        }
        __syncthreads();

        // ---- mma with fragment reuse: Ah,Bh -> hh; +Bl -> hl; +Al -> lh ----
        #pragma unroll
        for (int kk = 0; kk < 2; kk++) {
            const uint32_t aa = sb + O_AH + b * 10240 + aLane + kk * 32;
            const uint32_t bb = sb + O_BH + bLane + kk * 32;
            uint32_t ah0[4], ah1[4], bh0[4], bh1[4];
            ldsm4(ah0, aa + m0 * PBY);
            ldsm4(ah1, aa + (m0 + 16) * PBY);
            ldsm4(bh0, bb + n0 * PBY);
            ldsm4(bh1, bb + (n0 + 16) * PBY);
            mma8x(acc, ah0, ah1, bh0, bh1);
            if (PASSES == 3) {
                const uint32_t bbl = sb + O_BL + bLane + kk * 32;
                uint32_t bl0[4], bl1[4];
                ldsm4(bl0, bbl + n0 * PBY);
                ldsm4(bl1, bbl + (n0 + 16) * PBY);
                mma8x(acc, ah0, ah1, bl0, bl1);  // Ah x Bl
                const uint32_t aal = sb + O_ALO + b * 10240 + aLane + kk * 32;
                uint32_t al0[4], al1[4];
                ldsm4(al0, aal + m0 * PBY);
                ldsm4(al1, aal + (m0 + 16) * PBY);
                mma8x(acc, al0, al1, bh0, bh1);  // Al x Bh
            }
        }
    }
}

__global__ void __launch_bounds__(256, 2)
csa_kernel(const float* __restrict__ feat, const float* __restrict__ pos,
           const float* __restrict__ Wq, const float* __restrict__ Wk,
           const float* __restrict__ Wv, float* __restrict__ out) {
    extern __shared__ char sm[];
    float* smf = (float*)sm;
    const uint32_t sb = smem_u32(sm);
    const int tid = threadIdx.x;
    const int lane = tid & 31;
    const int wid = tid >> 5;
    const int m0 = (wid >> 1) * 32;
    const int n0 = (wid & 1) * 32;
    const int mg = wid >> 1;
    const float NEG = __int_as_float(0xff800000);
    const float POS = __int_as_float(0x7f800000);
    const int R = O_RED / 4;

    // column sums of Wq (tid<128) and Wk (tid>=128), fp32
    {
        const float* W = (tid < 128) ? Wq : Wk;
        const int c = tid & 127;
        float s0 = 0.f, s1 = 0.f, s2 = 0.f, s3 = 0.f;
        #pragma unroll 4
        for (int o = 0; o < 128; o += 4) {
            s0 += __ldg(W + (o + 0) * 128 + c);
            s1 += __ldg(W + (o + 1) * 128 + c);
            s2 += __ldg(W + (o + 2) * 128 + c);
            s3 += __ldg(W + (o + 3) * 128 + c);
        }
        smf[(tid < 128 ? O_WQ / 4 : O_WK / 4 - 128) + tid] = (s0 + s1) + (s2 + s3);
    }
    __syncthreads();

    const size_t base =
        (size_t)blockIdx.y * (128u * 16384u) + (size_t)blockIdx.x * 64u;
    const uint32_t aLane = (uint32_t)((lane & 15) * PBY + (lane >> 4) * 16);
    const uint32_t bLane =
        (uint32_t)(((((lane >> 4) << 3) + (lane & 7)) * PBY) + (((lane >> 3) & 1) << 4));

    float acc[2][4][4];
    #pragma unroll
    for (int a = 0; a < 2; a++)
        #pragma unroll
        for (int b = 0; b < 4; b++)
            #pragma unroll
            for (int c = 0; c < 4; c++) acc[a][b][c] = 0.f;

    // ---------------- GEMM 1: K = Wk * pos (3-pass split) ----------------
    float sqp = 0.f, Sp = 0.f;
    run_gemm<3, true>(pos, base, sm, sb, tid, m0, n0, aLane, bLane, acc,
                      &sqp, &Sp);

    // Early GEMM2 prologue: chunk-0 DMA flies during the epilogue.
    dma_chunk<1>(sb, 0, 0, feat, base, tid);
    CP_COMMIT();

    // ---------------- register-resident softmax epilogue ----------------
    float* sE = smf + O_SE / 4;
    // per-thread per-column partial max/min from acc
    float pmx[8], pmn[8];
    #pragma unroll
    for (int nt = 0; nt < 4; nt++)
        #pragma unroll
        for (int h = 0; h < 2; h++) {
            float v0 = acc[0][nt][h], v1 = acc[0][nt][2 + h];
            float v2 = acc[1][nt][h], v3 = acc[1][nt][2 + h];
            pmx[nt * 2 + h] = fmaxf(fmaxf(v0, v1), fmaxf(v2, v3));
            pmn[nt * 2 + h] = fminf(fminf(v0, v1), fminf(v2, v3));
        }
    #pragma unroll
    for (int i = 0; i < 8; i++) {
        #pragma unroll
        for (int d = 4; d <= 16; d <<= 1) {
            pmx[i] = fmaxf(pmx[i], __shfl_xor_sync(0xffffffffu, pmx[i], d));
            pmn[i] = fminf(pmn[i], __shfl_xor_sync(0xffffffffu, pmn[i], d));
        }
    }
    smf[R + tid] = sqp;
    smf[R + 256 + tid] = Sp;
    if (lane < 4) {
        #pragma unroll
        for (int nt = 0; nt < 4; nt++)
            #pragma unroll
            for (int h = 0; h < 2; h++) {
                int col = n0 + nt * 8 + 2 * lane + h;
                smf[R + 512 + mg * 64 + col] = pmx[nt * 2 + h];
                smf[R + 768 + mg * 64 + col] = pmn[nt * 2 + h];
            }
    }
    __syncthreads();
    if (tid < 64) {
        float sq = 0.f, S = 0.f, mx = NEG, mn = POS;
        #pragma unroll
        for (int g = 0; g < 4; g++) {
            sq += smf[R + g * 64 + tid];
            S += smf[R + 256 + g * 64 + tid];
            mx = fmaxf(mx, smf[R + 512 + g * 64 + tid]);
            mn = fminf(mn, smf[R + 768 + g * 64 + tid]);
        }
        float al = sq / (1e-9f + sq * S);
        smf[O_AL / 4 + tid] = al;
        smf[O_M / 4 + tid] = fmaxf(al * mx, al * mn);
    }
    __syncthreads();
    // exp from registers; write e into sE once; accumulate denominators
    float pd[8];
    #pragma unroll
    for (int i = 0; i < 8; i++) pd[i] = 0.f;
    #pragma unroll
    for (int nt = 0; nt < 4; nt++)
        #pragma unroll
        for (int h = 0; h < 2; h++) {
            int col = n0 + nt * 8 + 2 * (lane & 3) + h;
            float al = smf[O_AL / 4 + col], mv = smf[O_M / 4 + col];
            #pragma unroll
            for (int mt = 0; mt < 2; mt++)
                #pragma unroll
                for (int half = 0; half < 2; half++) {
                    float e = __expf(fmaf(al, acc[mt][nt][2 * half + h], -mv));
                    acc[mt][nt][2 * half + h] = e;
                    pd[nt * 2 + h] += e;
                }
        }
    #pragma unroll
    for (int mt = 0; mt < 2; mt++)
        #pragma unroll
        for (int nt = 0; nt < 4; nt++) {
            int r = m0 + mt * 16 + (lane >> 2);
            int col = n0 + nt * 8 + 2 * (lane & 3);
            *(float2*)(sE + r * SEP + col) =
                make_float2(acc[mt][nt][0], acc[mt][nt][1]);
            *(float2*)(sE + (r + 8) * SEP + col) =
                make_float2(acc[mt][nt][2], acc[mt][nt][3]);
        }
    #pragma unroll
    for (int i = 0; i < 8; i++)
        #pragma unroll
        for (int d = 4; d <= 16; d <<= 1)
            pd[i] += __shfl_xor_sync(0xffffffffu, pd[i], d);
    if (lane < 4) {
        #pragma unroll
        for (int nt = 0; nt < 4; nt++)
            #pragma unroll
            for (int h = 0; h < 2; h++)
                smf[R + 512 + mg * 64 + n0 + nt * 8 + 2 * lane + h] =
                    pd[nt * 2 + h];
    }
    __syncthreads();
    if (tid < 64) {
        float d = 0.f;
        #pragma unroll
        for (int g = 0; g < 4; g++) d += smf[R + 512 + g * 64 + tid];
        smf[O_INV / 4 + tid] = 1.0f / d;
    }
    // (GEMM2's first in-loop sync orders s_inv/sE before later readers)

    // ---------------- GEMM 2: V = Wv * feat (1-pass hi) ----------------
    #pragma unroll
    for (int a = 0; a < 2; a++)
        #pragma unroll
        for (int b = 0; b < 4; b++)
            #pragma unroll
            for (int c = 0; c < 4; c++) acc[a][b][c] = 0.f;
    run_gemm<1, false>(feat, base, sm, sb, tid, m0, n0, aLane, bLane, acc,
                       nullptr, nullptr);

    // ---------------- apply: out = (e*inv)*V + feat ----------------
    const float* s_inv = smf + O_INV / 4;
    #pragma unroll
    for (int mt = 0; mt < 2; mt++)
        #pragma unroll
        for (int nt = 0; nt < 4; nt++) {
            int rr = m0 + mt * 16 + (lane >> 2);
            int col = n0 + nt * 8 + 2 * (lane & 3);
            float2 inv2 = *(const float2*)(s_inv + col);
            #pragma unroll
            for (int half = 0; half < 2; half++) {
                int r = rr + half * 8;
                float d0 = acc[mt][nt][2 * half];
                float d1 = acc[mt][nt][2 * half + 1];
                float2 e2 = *(const float2*)(sE + r * SEP + col);
                float2 f2 =
                    __ldg((const float2*)(feat + base + (size_t)r * 16384 + col));
                float2 o;
                o.x = fmaf(e2.x * inv2.x, d0, f2.x);
                o.y = fmaf(e2.y * inv2.y, d1, f2.y);
                *(float2*)(out + base + (size_t)r * 16384 + col) = o;
            }
        }
}

extern "C" void kernel_launch(void* const* d_in, const int* in_sizes, int n_in,
                              void* d_out, int out_size) {
    const float* feat = (const float*)d_in[0];
    const float* pos  = (const float*)d_in[1];
    const float* Wq   = (const float*)d_in[2];
    const float* Wk   = (const float*)d_in[3];
    const float* Wv   = (const float*)d_in[4];
    float* out = (float*)d_out;

    prep_kernel<<<4, 512>>>(Wk, Wv);
    cudaFuncSetAttribute(csa_kernel, cudaFuncAttributeMaxDynamicSharedMemorySize,
                         SMEM_BYTES);
    dim3 grid(16384 / 64, 16);
    csa_kernel<<<grid, 256, SMEM_BYTES>>>(feat, pos, Wq, Wk, Wv, out);
}